// round 7
// baseline (speedup 1.0000x reference)
#include <cuda_runtime.h>
#include <cuda_bf16.h>

#define NN 50000
#define EE 1600000
#define DH 64
#define BN_EPS 1e-5f
#define SCAN_B 1024
#define NBLK 49              // ceil(50000/1024)

// ---------------- scratch (static device globals; no runtime alloc) ----------
__device__ __align__(16) float g_wmix[EE];        // mixed edge weights
__device__ __align__(16) float g_deg[NN];         // weighted degree -> dinv in place
__device__ __align__(16) int   g_srcA[EE];        // int32 src
__device__ __align__(16) int   g_dstA[EE];        // int32 dst
__device__ __align__(16) int   g_cnt[NN];         // in-degree histogram
__device__ __align__(16) int   g_cur[NN];         // fill cursors
__device__ __align__(16) int   g_off[NN + 1];     // CSR row offsets (by dst)
__device__ __align__(16) int   g_bsum[64];        // scan block sums
__device__ __align__(16) int   g_csrc[EE];        // CSR: src per in-edge
__device__ __align__(16) float g_cnorm[EE];       // CSR: full GCN norm per in-edge
__device__ __align__(16) float g_bufA[NN * DH];   // GEMM output (h)
__device__ __align__(16) float g_bufB[NN * DH];   // gather output
__device__ __align__(16) float g_bufC[NN * DH];   // BN+ReLU output of layer 1
__device__ __align__(16) float g_stats[256];      // sums/sumsqs for both BN layers

// ---------------- init ------------------------------------------------------
__global__ void k_init() {
    int i = blockIdx.x * blockDim.x + threadIdx.x;
    if (i < NN) { g_deg[i] = 1.0f; g_cnt[i] = 0; g_cur[i] = 0; }
    if (i < 256) g_stats[i] = 0.0f;
}

// ---------------- mix weights, degree + count -------------------------------
// edge_index is INT32 on device (JAX silently downgrades int64 without x64).
__global__ void k_mixdeg(const int* __restrict__ ei,
                         const float* __restrict__ wsc,
                         const float* __restrict__ wfc,
                         const float* __restrict__ alpha) {
    int e = blockIdx.x * blockDim.x + threadIdx.x;
    if (e >= EE) return;
    float a = 1.0f / (1.0f + expf(-alpha[0]));
    float w = a * wsc[e] + (1.0f - a) * wfc[e];
    g_wmix[e] = w;
    int s = ei[e];          // row 0: src
    int d = ei[EE + e];     // row 1: dst
    g_srcA[e] = s;
    g_dstA[e] = d;
    atomicAdd(&g_deg[d], w);
    atomicAdd(&g_cnt[d], 1);
}

__global__ void k_dinv() {
    int i = blockIdx.x * blockDim.x + threadIdx.x;
    if (i >= NN) return;
    float dg = g_deg[i];
    g_deg[i] = (dg > 0.0f) ? rsqrtf(fmaxf(dg, 1e-12f)) : 0.0f;
}

// ---------------- 3-phase exclusive scan of g_cnt -> g_off ------------------
__global__ void k_scan1() {   // grid NBLK, block 1024: inclusive scan per block
    __shared__ int s[SCAN_B];
    int i = blockIdx.x * SCAN_B + threadIdx.x;
    int v = (i < NN) ? g_cnt[i] : 0;
    s[threadIdx.x] = v;
    __syncthreads();
    for (int o = 1; o < SCAN_B; o <<= 1) {
        int t = (threadIdx.x >= o) ? s[threadIdx.x - o] : 0;
        __syncthreads();
        s[threadIdx.x] += t;
        __syncthreads();
    }
    if (i < NN) g_off[i] = s[threadIdx.x];        // inclusive, temp
    if (threadIdx.x == SCAN_B - 1) g_bsum[blockIdx.x] = s[SCAN_B - 1];
}

__global__ void k_scan2() {   // 1 thread: exclusive scan of block sums
    if (threadIdx.x == 0) {
        int run = 0;
        for (int b = 0; b < NBLK; b++) { int t = g_bsum[b]; g_bsum[b] = run; run += t; }
        g_off[NN] = run;      // == EE
    }
}

__global__ void k_scan3() {   // convert to exclusive with block base
    int i = blockIdx.x * SCAN_B + threadIdx.x;
    if (i >= NN) return;
    int incl = g_off[i];
    int v = g_cnt[i];
    g_off[i] = g_bsum[i / SCAN_B] + incl - v;
}

// ---------------- fill CSR (src + full norm per in-edge) --------------------
__global__ void k_fill() {
    int e = blockIdx.x * blockDim.x + threadIdx.x;
    if (e >= EE) return;
    int s = g_srcA[e];
    int d = g_dstA[e];
    int pos = g_off[d] + atomicAdd(&g_cur[d], 1);
    g_csrc[pos] = s;
    g_cnorm[pos] = g_deg[s] * g_wmix[e] * g_deg[d];
}

// ---------------- small GEMM: bufA[NN,64] = X[NN,K] @ W[K,64] ----------------
template <int K, bool EXT>
__global__ void k_gemm(const float* __restrict__ Xext, const float* __restrict__ W) {
    __shared__ __align__(16) float sW[K][64];
    __shared__ __align__(16) float sx[16][K + 4];
    const float* __restrict__ X = EXT ? Xext : g_bufC;

    int tid = threadIdx.x;
    for (int i = tid; i < K * 64; i += 256)
        sW[i >> 6][i & 63] = W[i];

    int row0 = blockIdx.x * 16;
    for (int i = tid; i < 16 * K; i += 256) {
        int r = i / K, c = i % K;
        int gr = row0 + r;
        sx[r][c] = (gr < NN) ? X[(long)gr * K + c] : 0.0f;
    }
    __syncthreads();

    int r = tid >> 4;
    int cg = (tid & 15) << 2;
    float a0 = 0.f, a1 = 0.f, a2 = 0.f, a3 = 0.f;
#pragma unroll
    for (int k = 0; k < K; k++) {
        float xv = sx[r][k];
        float4 wv = *(const float4*)&sW[k][cg];
        a0 = fmaf(xv, wv.x, a0);
        a1 = fmaf(xv, wv.y, a1);
        a2 = fmaf(xv, wv.z, a2);
        a3 = fmaf(xv, wv.w, a3);
    }
    int gr = row0 + r;
    if (gr < NN) {
        float4 v = make_float4(a0, a1, a2, a3);
        *(float4*)(g_bufA + (long)gr * DH + cg) = v;
    }
}

// ---------------- gather: bufB[n] = dinv[n]^2*bufA[n] + sum_in bufA[s]*norm --
// One warp per node. Lanes split: half h handles edges beg+h, beg+h+2, ...;
// within a half, 16 lanes * float4 cover the 64-col row. Final shfl-combine.
__global__ void k_gather() {
    int warp = (blockIdx.x * blockDim.x + threadIdx.x) >> 5;
    if (warp >= NN) return;
    int lane = threadIdx.x & 31;
    int half = lane >> 4;
    int c4 = (lane & 15) << 2;

    int beg = g_off[warp];
    int end = g_off[warp + 1];

    float4 acc = make_float4(0.f, 0.f, 0.f, 0.f);
    if (half == 0) {                       // self loop
        float di = g_deg[warp];
        float w = di * di;
        float4 v = *(const float4*)(g_bufA + (long)warp * DH + c4);
        acc.x = v.x * w; acc.y = v.y * w; acc.z = v.z * w; acc.w = v.w * w;
    }

    for (int e = beg + half; e < end; e += 2) {
        int s = __ldg(&g_csrc[e]);
        float nr = __ldg(&g_cnorm[e]);
        float4 v = *(const float4*)(g_bufA + (long)s * DH + c4);
        acc.x = fmaf(v.x, nr, acc.x);
        acc.y = fmaf(v.y, nr, acc.y);
        acc.z = fmaf(v.z, nr, acc.z);
        acc.w = fmaf(v.w, nr, acc.w);
    }

    acc.x += __shfl_xor_sync(0xFFFFFFFFu, acc.x, 16);
    acc.y += __shfl_xor_sync(0xFFFFFFFFu, acc.y, 16);
    acc.z += __shfl_xor_sync(0xFFFFFFFFu, acc.z, 16);
    acc.w += __shfl_xor_sync(0xFFFFFFFFu, acc.w, 16);

    if (half == 0)
        *(float4*)(g_bufB + (long)warp * DH + c4) = acc;
}

// ---------------- BN stats: per-channel sum / sumsq over bufB ----------------
__global__ void k_bnstats(int off) {
    __shared__ float ssum[256];
    __shared__ float ssq[256];
    int c = threadIdx.x & 63;
    int g = threadIdx.x >> 6;
    float s = 0.f, q = 0.f;
    for (int row = blockIdx.x * 4 + g; row < NN; row += gridDim.x * 4) {
        float v = g_bufB[row * DH + c];
        s += v;
        q += v * v;
    }
    ssum[threadIdx.x] = s;
    ssq[threadIdx.x]  = q;
    __syncthreads();
    if (g == 0) {
        s = ssum[c] + ssum[64 + c] + ssum[128 + c] + ssum[192 + c];
        q = ssq[c]  + ssq[64 + c]  + ssq[128 + c]  + ssq[192 + c];
        atomicAdd(&g_stats[off + c], s);
        atomicAdd(&g_stats[off + 64 + c], q);
    }
}

// ---------------- BN normalize + ReLU (bias cancels against the mean) -------
template <bool TO_OUT>
__global__ void k_bnrelu(int off, const float* __restrict__ gamma,
                         const float* __restrict__ beta, float* __restrict__ out) {
    int idx = blockIdx.x * blockDim.x + threadIdx.x;
    if (idx >= NN * DH) return;
    int c = idx & 63;
    const float invN = 1.0f / (float)NN;
    float mean = g_stats[off + c] * invN;
    float var  = g_stats[off + 64 + c] * invN - mean * mean;
    float sc = gamma[c] * rsqrtf(var + BN_EPS);
    float sh = beta[c] - mean * sc;
    float v = fmaxf(fmaf(g_bufB[idx], sc, sh), 0.0f);
    if (TO_OUT) out[idx] = v;
    else        g_bufC[idx] = v;
}

// ---------------- launch ------------------------------------------------------
extern "C" void kernel_launch(void* const* d_in, const int* in_sizes, int n_in,
                              void* d_out, int out_size) {
    const float* x     = (const float*)d_in[0];
    const int*   ei_sc = (const int*)d_in[1];      // int32! (JAX x64 disabled)
    const float* w_sc  = (const float*)d_in[2];
    /* d_in[3] edge_index_fc unused (matches reference) */
    const float* w_fc  = (const float*)d_in[4];
    const float* alpha = (const float*)d_in[5];
    const float* W1    = (const float*)d_in[6];
    /* d_in[7] b1 cancels in BN */
    const float* W2    = (const float*)d_in[8];
    /* d_in[9] b2 cancels in BN */
    const float* g1    = (const float*)d_in[10];
    const float* be1   = (const float*)d_in[11];
    const float* g2    = (const float*)d_in[12];
    const float* be2   = (const float*)d_in[13];
    float* out = (float*)d_out;

    const int T = 256;
    int gridNV = (NN * DH + T - 1) / T;          // 12500
    int gridE  = (EE + T - 1) / T;               // 6250
    int gridN  = (NN + T - 1) / T;               // 196
    int gridGm = (NN + 15) / 16;                 // 3125
    int gridGa = (NN + 7) / 8;                   // 6250 (8 warps/block)

    // CSR build (shared by both layers)
    k_init<<<gridN, T>>>();
    k_mixdeg<<<gridE, T>>>(ei_sc, w_sc, w_fc, alpha);
    k_dinv<<<gridN, T>>>();
    k_scan1<<<NBLK, SCAN_B>>>();
    k_scan2<<<1, 32>>>();
    k_scan3<<<NBLK, SCAN_B>>>();
    k_fill<<<gridE, T>>>();

    // Layer 1
    k_gemm<128, true><<<gridGm, T>>>(x, W1);
    k_gather<<<gridGa, T>>>();
    k_bnstats<<<256, T>>>(0);
    k_bnrelu<false><<<gridNV, T>>>(0, g1, be1, nullptr);

    // Layer 2
    k_gemm<64, false><<<gridGm, T>>>(nullptr, W2);
    k_gather<<<gridGa, T>>>();
    k_bnstats<<<256, T>>>(128);
    k_bnrelu<true><<<gridNV, T>>>(128, g2, be2, out);
}

// round 14
// speedup vs baseline: 1.0616x; 1.0616x over previous
#include <cuda_runtime.h>
#include <cuda_bf16.h>

#define NN 50000
#define EE 1600000
#define DH 64
#define BN_EPS 1e-5f
#define SCAN_B 1024
#define NBLK 49              // ceil(50000/1024)

// ---------------- scratch (static device globals; no runtime alloc) ----------
__device__ __align__(16) float g_wmix[EE];        // mixed edge weights
__device__ __align__(16) float g_deg[NN];         // weighted degree -> dinv in place
__device__ __align__(16) int   g_srcA[EE];        // int32 src
__device__ __align__(16) int   g_dstA[EE];        // int32 dst
__device__ __align__(16) int   g_cnt[NN];         // in-degree histogram
__device__ __align__(16) int   g_cur[NN];         // fill cursors
__device__ __align__(16) int   g_off[NN + 1];     // CSR row offsets (by dst)
__device__ __align__(16) int   g_bsum[64];        // scan block sums
__device__ __align__(16) int2  g_rec[EE];         // CSR: {src, norm-bits} per in-edge
__device__ __align__(16) float g_bufA[NN * DH];   // GEMM output (h)
__device__ __align__(16) float g_bufB[NN * DH];   // gather output
__device__ __align__(16) float g_stats[256];      // sums/sumsqs for both BN layers

// ---------------- init ------------------------------------------------------
__global__ void k_init() {
    int i = blockIdx.x * blockDim.x + threadIdx.x;
    if (i < NN) { g_deg[i] = 1.0f; g_cnt[i] = 0; g_cur[i] = 0; }
    if (i < 256) g_stats[i] = 0.0f;
}

// ---------------- mix weights, degree + count -------------------------------
// edge_index is INT32 on device (JAX silently downgrades int64 without x64).
__global__ void k_mixdeg(const int* __restrict__ ei,
                         const float* __restrict__ wsc,
                         const float* __restrict__ wfc,
                         const float* __restrict__ alpha) {
    int e = blockIdx.x * blockDim.x + threadIdx.x;
    if (e >= EE) return;
    float a = 1.0f / (1.0f + expf(-alpha[0]));
    float w = a * wsc[e] + (1.0f - a) * wfc[e];
    g_wmix[e] = w;
    int s = ei[e];          // row 0: src
    int d = ei[EE + e];     // row 1: dst
    g_srcA[e] = s;
    g_dstA[e] = d;
    atomicAdd(&g_deg[d], w);
    atomicAdd(&g_cnt[d], 1);
}

// ---------------- scan1 (+ fused dinv): per-block inclusive scan -------------
__global__ void k_scan1() {
    __shared__ int s[SCAN_B];
    int i = blockIdx.x * SCAN_B + threadIdx.x;
    int v = (i < NN) ? g_cnt[i] : 0;
    s[threadIdx.x] = v;
    // fused dinv (independent of the scan; mixdeg is complete by now)
    if (i < NN) {
        float dg = g_deg[i];
        g_deg[i] = (dg > 0.0f) ? rsqrtf(fmaxf(dg, 1e-12f)) : 0.0f;
    }
    __syncthreads();
    for (int o = 1; o < SCAN_B; o <<= 1) {
        int t = (threadIdx.x >= o) ? s[threadIdx.x - o] : 0;
        __syncthreads();
        s[threadIdx.x] += t;
        __syncthreads();
    }
    if (i < NN) g_off[i] = s[threadIdx.x];        // inclusive, temp
    if (threadIdx.x == SCAN_B - 1) g_bsum[blockIdx.x] = s[SCAN_B - 1];
}

__global__ void k_scan2() {   // 1 thread: exclusive scan of block sums
    if (threadIdx.x == 0) {
        int run = 0;
        for (int b = 0; b < NBLK; b++) { int t = g_bsum[b]; g_bsum[b] = run; run += t; }
        g_off[NN] = run;      // == EE
    }
}

__global__ void k_scan3() {   // convert to exclusive with block base
    int i = blockIdx.x * SCAN_B + threadIdx.x;
    if (i >= NN) return;
    int incl = g_off[i];
    int v = g_cnt[i];
    g_off[i] = g_bsum[i / SCAN_B] + incl - v;
}

// ---------------- fill CSR: interleaved {src, norm} record ------------------
__global__ void k_fill() {
    int e = blockIdx.x * blockDim.x + threadIdx.x;
    if (e >= EE) return;
    int s = g_srcA[e];
    int d = g_dstA[e];
    int pos = g_off[d] + atomicAdd(&g_cur[d], 1);
    float nr = g_deg[s] * g_wmix[e] * g_deg[d];
    g_rec[pos] = make_int2(s, __float_as_int(nr));
}

// ---------------- GEMM1: bufA[NN,64] = X[NN,128] @ W1[128,64] ----------------
__global__ void k_gemm1(const float* __restrict__ X, const float* __restrict__ W) {
    const int K = 128;
    __shared__ __align__(16) float sW[K][64];
    __shared__ __align__(16) float sx[16][K + 4];

    int tid = threadIdx.x;
    for (int i = tid; i < K * 64; i += 256)
        sW[i >> 6][i & 63] = W[i];

    int row0 = blockIdx.x * 16;
    for (int i = tid; i < 16 * K; i += 256) {
        int r = i / K, c = i % K;
        int gr = row0 + r;
        sx[r][c] = (gr < NN) ? X[(long)gr * K + c] : 0.0f;
    }
    __syncthreads();

    int r = tid >> 4;
    int cg = (tid & 15) << 2;
    float a0 = 0.f, a1 = 0.f, a2 = 0.f, a3 = 0.f;
#pragma unroll
    for (int k = 0; k < K; k++) {
        float xv = sx[r][k];
        float4 wv = *(const float4*)&sW[k][cg];
        a0 = fmaf(xv, wv.x, a0);
        a1 = fmaf(xv, wv.y, a1);
        a2 = fmaf(xv, wv.z, a2);
        a3 = fmaf(xv, wv.w, a3);
    }
    int gr = row0 + r;
    if (gr < NN) {
        float4 v = make_float4(a0, a1, a2, a3);
        *(float4*)(g_bufA + (long)gr * DH + cg) = v;
    }
}

// ---------------- GEMM2 (BN1+ReLU fused into the X load) --------------------
// bufA[NN,64] = relu(BN1(bufB)) @ W2[64,64]
__global__ void k_gemm2(const float* __restrict__ W,
                        const float* __restrict__ gamma,
                        const float* __restrict__ beta) {
    const int K = 64;
    __shared__ __align__(16) float sW[K][64];
    __shared__ __align__(16) float sx[16][K + 4];
    __shared__ float sSc[64], sSh[64];

    int tid = threadIdx.x;
    if (tid < 64) {
        const float invN = 1.0f / (float)NN;
        float mean = g_stats[tid] * invN;
        float var  = g_stats[64 + tid] * invN - mean * mean;
        float sc = gamma[tid] * rsqrtf(var + BN_EPS);
        sSc[tid] = sc;
        sSh[tid] = beta[tid] - mean * sc;
    }
    for (int i = tid; i < K * 64; i += 256)
        sW[i >> 6][i & 63] = W[i];
    __syncthreads();

    int row0 = blockIdx.x * 16;
    for (int i = tid; i < 16 * K; i += 256) {
        int r = i / K, c = i % K;
        int gr = row0 + r;
        float v = (gr < NN) ? g_bufB[(long)gr * K + c] : 0.0f;
        sx[r][c] = fmaxf(fmaf(v, sSc[c], sSh[c]), 0.0f);
    }
    __syncthreads();

    int r = tid >> 4;
    int cg = (tid & 15) << 2;
    float a0 = 0.f, a1 = 0.f, a2 = 0.f, a3 = 0.f;
#pragma unroll
    for (int k = 0; k < K; k++) {
        float xv = sx[r][k];
        float4 wv = *(const float4*)&sW[k][cg];
        a0 = fmaf(xv, wv.x, a0);
        a1 = fmaf(xv, wv.y, a1);
        a2 = fmaf(xv, wv.z, a2);
        a3 = fmaf(xv, wv.w, a3);
    }
    int gr = row0 + r;
    if (gr < NN) {
        float4 v = make_float4(a0, a1, a2, a3);
        *(float4*)(g_bufA + (long)gr * DH + cg) = v;
    }
}

// ---------------- gather: bufB[n] = dinv[n]^2*bufA[n] + sum_in bufA[s]*norm --
// One warp per node; each half-warp takes a contiguous half of the edge range.
// 4-deep manual unroll -> 4 independent index->data load chains (MLP 4).
__global__ void k_gather() {
    int warp = (blockIdx.x * blockDim.x + threadIdx.x) >> 5;
    if (warp >= NN) return;
    int lane = threadIdx.x & 31;
    int half = lane >> 4;
    int c4 = (lane & 15) << 2;

    int beg = g_off[warp];
    int end = g_off[warp + 1];
    int len = end - beg;
    int cnt0 = (len + 1) >> 1;
    int hb = beg + (half ? cnt0 : 0);
    int he = half ? end : beg + cnt0;

    float4 acc = make_float4(0.f, 0.f, 0.f, 0.f);
    if (half == 0) {                       // self loop
        float di = g_deg[warp];
        float w = di * di;
        float4 v = *(const float4*)(g_bufA + (long)warp * DH + c4);
        acc.x = v.x * w; acc.y = v.y * w; acc.z = v.z * w; acc.w = v.w * w;
    }

    int e = hb;
    for (; e + 4 <= he; e += 4) {
        int2 r0 = __ldg(&g_rec[e]);
        int2 r1 = __ldg(&g_rec[e + 1]);
        int2 r2 = __ldg(&g_rec[e + 2]);
        int2 r3 = __ldg(&g_rec[e + 3]);
        float4 v0 = *(const float4*)(g_bufA + (long)r0.x * DH + c4);
        float4 v1 = *(const float4*)(g_bufA + (long)r1.x * DH + c4);
        float4 v2 = *(const float4*)(g_bufA + (long)r2.x * DH + c4);
        float4 v3 = *(const float4*)(g_bufA + (long)r3.x * DH + c4);
        float n0 = __int_as_float(r0.y), n1 = __int_as_float(r1.y);
        float n2 = __int_as_float(r2.y), n3 = __int_as_float(r3.y);
        acc.x = fmaf(v0.x, n0, acc.x); acc.y = fmaf(v0.y, n0, acc.y);
        acc.z = fmaf(v0.z, n0, acc.z); acc.w = fmaf(v0.w, n0, acc.w);
        acc.x = fmaf(v1.x, n1, acc.x); acc.y = fmaf(v1.y, n1, acc.y);
        acc.z = fmaf(v1.z, n1, acc.z); acc.w = fmaf(v1.w, n1, acc.w);
        acc.x = fmaf(v2.x, n2, acc.x); acc.y = fmaf(v2.y, n2, acc.y);
        acc.z = fmaf(v2.z, n2, acc.z); acc.w = fmaf(v2.w, n2, acc.w);
        acc.x = fmaf(v3.x, n3, acc.x); acc.y = fmaf(v3.y, n3, acc.y);
        acc.z = fmaf(v3.z, n3, acc.z); acc.w = fmaf(v3.w, n3, acc.w);
    }
    for (; e < he; e++) {
        int2 r = __ldg(&g_rec[e]);
        float nr = __int_as_float(r.y);
        float4 v = *(const float4*)(g_bufA + (long)r.x * DH + c4);
        acc.x = fmaf(v.x, nr, acc.x);
        acc.y = fmaf(v.y, nr, acc.y);
        acc.z = fmaf(v.z, nr, acc.z);
        acc.w = fmaf(v.w, nr, acc.w);
    }

    acc.x += __shfl_xor_sync(0xFFFFFFFFu, acc.x, 16);
    acc.y += __shfl_xor_sync(0xFFFFFFFFu, acc.y, 16);
    acc.z += __shfl_xor_sync(0xFFFFFFFFu, acc.z, 16);
    acc.w += __shfl_xor_sync(0xFFFFFFFFu, acc.w, 16);

    if (half == 0)
        *(float4*)(g_bufB + (long)warp * DH + c4) = acc;
}

// ---------------- BN stats: per-channel sum / sumsq over bufB ----------------
__global__ void k_bnstats(int off) {
    __shared__ float ssum[256];
    __shared__ float ssq[256];
    int c = threadIdx.x & 63;
    int g = threadIdx.x >> 6;
    float s = 0.f, q = 0.f;
    for (int row = blockIdx.x * 4 + g; row < NN; row += gridDim.x * 4) {
        float v = g_bufB[row * DH + c];
        s += v;
        q += v * v;
    }
    ssum[threadIdx.x] = s;
    ssq[threadIdx.x]  = q;
    __syncthreads();
    if (g == 0) {
        s = ssum[c] + ssum[64 + c] + ssum[128 + c] + ssum[192 + c];
        q = ssq[c]  + ssq[64 + c]  + ssq[128 + c]  + ssq[192 + c];
        atomicAdd(&g_stats[off + c], s);
        atomicAdd(&g_stats[off + 64 + c], q);
    }
}

// ---------------- final BN2 + ReLU -> out ------------------------------------
__global__ void k_bnrelu_out(const float* __restrict__ gamma,
                             const float* __restrict__ beta,
                             float* __restrict__ out) {
    int idx = blockIdx.x * blockDim.x + threadIdx.x;
    if (idx >= NN * DH) return;
    int c = idx & 63;
    const float invN = 1.0f / (float)NN;
    float mean = g_stats[128 + c] * invN;
    float var  = g_stats[192 + c] * invN - mean * mean;
    float sc = gamma[c] * rsqrtf(var + BN_EPS);
    float sh = beta[c] - mean * sc;
    out[idx] = fmaxf(fmaf(g_bufB[idx], sc, sh), 0.0f);
}

// ---------------- launch ------------------------------------------------------
extern "C" void kernel_launch(void* const* d_in, const int* in_sizes, int n_in,
                              void* d_out, int out_size) {
    const float* x     = (const float*)d_in[0];
    const int*   ei_sc = (const int*)d_in[1];      // int32! (JAX x64 disabled)
    const float* w_sc  = (const float*)d_in[2];
    /* d_in[3] edge_index_fc unused (matches reference) */
    const float* w_fc  = (const float*)d_in[4];
    const float* alpha = (const float*)d_in[5];
    const float* W1    = (const float*)d_in[6];
    /* d_in[7] b1 cancels in BN */
    const float* W2    = (const float*)d_in[8];
    /* d_in[9] b2 cancels in BN */
    const float* g1    = (const float*)d_in[10];
    const float* be1   = (const float*)d_in[11];
    const float* g2    = (const float*)d_in[12];
    const float* be2   = (const float*)d_in[13];
    float* out = (float*)d_out;

    const int T = 256;
    int gridNV = (NN * DH + T - 1) / T;          // 12500
    int gridE  = (EE + T - 1) / T;               // 6250
    int gridN  = (NN + T - 1) / T;               // 196
    int gridGm = (NN + 15) / 16;                 // 3125
    int gridGa = (NN + 7) / 8;                   // 6250 (8 warps/block)

    // CSR build (shared by both layers)
    k_init<<<gridN, T>>>();
    k_mixdeg<<<gridE, T>>>(ei_sc, w_sc, w_fc, alpha);
    k_scan1<<<NBLK, SCAN_B>>>();                  // + fused dinv
    k_scan2<<<1, 32>>>();
    k_scan3<<<NBLK, SCAN_B>>>();
    k_fill<<<gridE, T>>>();

    // Layer 1
    k_gemm1<<<gridGm, T>>>(x, W1);
    k_gather<<<gridGa, T>>>();
    k_bnstats<<<256, T>>>(0);

    // Layer 2 (BN1+ReLU fused into GEMM2 load)
    k_gemm2<<<gridGm, T>>>(W2, g1, be1);
    k_gather<<<gridGa, T>>>();
    k_bnstats<<<256, T>>>(128);
    k_bnrelu_out<<<gridNV, T>>>(g2, be2, out);
}

// round 16
// speedup vs baseline: 1.0726x; 1.0103x over previous
#include <cuda_runtime.h>
#include <cuda_bf16.h>

#define NN 50000
#define EE 1600000
#define DH 64
#define BN_EPS 1e-5f
#define SCAN_B 1024
#define NBLK 49              // ceil(50000/1024)

// ---------------- scratch (static device globals; no runtime alloc) ----------
__device__ __align__(16) float g_wmix[EE];        // mixed edge weights
__device__ __align__(16) float g_deg[NN];         // weighted degree -> dinv in place
__device__ __align__(16) int   g_cnt[NN];         // in-degree histogram
__device__ __align__(16) int   g_cur[NN];         // fill cursors
__device__ __align__(16) int   g_off[NN + 1];     // CSR row offsets (by dst)
__device__ __align__(16) int   g_bsum[64];        // scan block sums
__device__ __align__(16) int2  g_rec[EE];         // CSR: {src, norm-bits} per in-edge
__device__ __align__(16) float g_bufA[NN * DH];   // GEMM output (h)
__device__ __align__(16) float g_bufB[NN * DH];   // gather output
__device__ __align__(16) float g_stats[256];      // sums/sumsqs for both BN layers

// ---------------- init ------------------------------------------------------
__global__ void k_init() {
    int i = blockIdx.x * blockDim.x + threadIdx.x;
    if (i < NN) { g_deg[i] = 1.0f; g_cnt[i] = 0; g_cur[i] = 0; }
    if (i < 256) g_stats[i] = 0.0f;
}

// ---------------- mix weights, degree + count -------------------------------
// edge_index is INT32 on device (JAX silently downgrades int64 without x64).
__global__ void k_mixdeg(const int* __restrict__ ei,
                         const float* __restrict__ wsc,
                         const float* __restrict__ wfc,
                         const float* __restrict__ alpha) {
    int e = blockIdx.x * blockDim.x + threadIdx.x;
    if (e >= EE) return;
    float a = 1.0f / (1.0f + expf(-alpha[0]));
    float w = a * wsc[e] + (1.0f - a) * wfc[e];
    g_wmix[e] = w;
    int d = ei[EE + e];     // row 1: dst
    atomicAdd(&g_deg[d], w);
    atomicAdd(&g_cnt[d], 1);
}

// ---------------- scan1 (+ fused dinv): per-block inclusive scan -------------
__global__ void k_scan1() {
    __shared__ int s[SCAN_B];
    int i = blockIdx.x * SCAN_B + threadIdx.x;
    int v = (i < NN) ? g_cnt[i] : 0;
    s[threadIdx.x] = v;
    // fused dinv (independent of the scan; mixdeg is complete by now)
    if (i < NN) {
        float dg = g_deg[i];
        g_deg[i] = (dg > 0.0f) ? rsqrtf(fmaxf(dg, 1e-12f)) : 0.0f;
    }
    __syncthreads();
    for (int o = 1; o < SCAN_B; o <<= 1) {
        int t = (threadIdx.x >= o) ? s[threadIdx.x - o] : 0;
        __syncthreads();
        s[threadIdx.x] += t;
        __syncthreads();
    }
    if (i < NN) g_off[i] = s[threadIdx.x];        // inclusive, temp
    if (threadIdx.x == SCAN_B - 1) g_bsum[blockIdx.x] = s[SCAN_B - 1];
}

// ---------------- scan3: per-block prefix of bsum (warp shfl) + finalize ----
// Replaces old scan2+scan3: each block computes its own base = sum of
// preceding block sums with one warp; last block also writes g_off[NN].
__global__ void k_scan3() {
    __shared__ int sbase;
    int b = blockIdx.x;
    if (threadIdx.x < 32) {
        int j0 = threadIdx.x, j1 = threadIdx.x + 32;
        int v0 = (j0 < NBLK) ? g_bsum[j0] : 0;
        int v1 = (j1 < NBLK) ? g_bsum[j1] : 0;
        int pre = ((j0 < b) ? v0 : 0) + ((j1 < b) ? v1 : 0);
        int tot = v0 + v1;
        for (int o = 16; o; o >>= 1) {
            pre += __shfl_xor_sync(0xFFFFFFFFu, pre, o);
            tot += __shfl_xor_sync(0xFFFFFFFFu, tot, o);
        }
        if (threadIdx.x == 0) {
            sbase = pre;
            if (b == NBLK - 1) g_off[NN] = tot;   // == EE
        }
    }
    __syncthreads();
    int i = b * SCAN_B + threadIdx.x;
    if (i < NN) g_off[i] = sbase + g_off[i] - g_cnt[i];   // exclusive global
}

// ---------------- fill CSR: interleaved {src, norm} record ------------------
// Re-reads edge_index directly (L2-resident input) — no srcA/dstA round-trip.
__global__ void k_fill(const int* __restrict__ ei) {
    int e = blockIdx.x * blockDim.x + threadIdx.x;
    if (e >= EE) return;
    int s = ei[e];
    int d = ei[EE + e];
    int pos = g_off[d] + atomicAdd(&g_cur[d], 1);
    float nr = g_deg[s] * g_wmix[e] * g_deg[d];
    g_rec[pos] = make_int2(s, __float_as_int(nr));
}

// ---------------- GEMM1: bufA[NN,64] = X[NN,128] @ W1[128,64] ----------------
__global__ void k_gemm1(const float* __restrict__ X, const float* __restrict__ W) {
    const int K = 128;
    __shared__ __align__(16) float sW[K][64];
    __shared__ __align__(16) float sx[16][K + 4];

    int tid = threadIdx.x;
    for (int i = tid; i < K * 64; i += 256)
        sW[i >> 6][i & 63] = W[i];

    int row0 = blockIdx.x * 16;
    for (int i = tid; i < 16 * K; i += 256) {
        int r = i / K, c = i % K;
        int gr = row0 + r;
        sx[r][c] = (gr < NN) ? X[(long)gr * K + c] : 0.0f;
    }
    __syncthreads();

    int r = tid >> 4;
    int cg = (tid & 15) << 2;
    float a0 = 0.f, a1 = 0.f, a2 = 0.f, a3 = 0.f;
#pragma unroll
    for (int k = 0; k < K; k++) {
        float xv = sx[r][k];
        float4 wv = *(const float4*)&sW[k][cg];
        a0 = fmaf(xv, wv.x, a0);
        a1 = fmaf(xv, wv.y, a1);
        a2 = fmaf(xv, wv.z, a2);
        a3 = fmaf(xv, wv.w, a3);
    }
    int gr = row0 + r;
    if (gr < NN) {
        float4 v = make_float4(a0, a1, a2, a3);
        *(float4*)(g_bufA + (long)gr * DH + cg) = v;
    }
}

// ---------------- GEMM2 (BN1+ReLU fused into the X load) --------------------
// bufA[NN,64] = relu(BN1(bufB)) @ W2[64,64]
__global__ void k_gemm2(const float* __restrict__ W,
                        const float* __restrict__ gamma,
                        const float* __restrict__ beta) {
    const int K = 64;
    __shared__ __align__(16) float sW[K][64];
    __shared__ __align__(16) float sx[16][K + 4];
    __shared__ float sSc[64], sSh[64];

    int tid = threadIdx.x;
    if (tid < 64) {
        const float invN = 1.0f / (float)NN;
        float mean = g_stats[tid] * invN;
        float var  = g_stats[64 + tid] * invN - mean * mean;
        float sc = gamma[tid] * rsqrtf(var + BN_EPS);
        sSc[tid] = sc;
        sSh[tid] = beta[tid] - mean * sc;
    }
    for (int i = tid; i < K * 64; i += 256)
        sW[i >> 6][i & 63] = W[i];
    __syncthreads();

    int row0 = blockIdx.x * 16;
    for (int i = tid; i < 16 * K; i += 256) {
        int r = i / K, c = i % K;
        int gr = row0 + r;
        float v = (gr < NN) ? g_bufB[(long)gr * K + c] : 0.0f;
        sx[r][c] = fmaxf(fmaf(v, sSc[c], sSh[c]), 0.0f);
    }
    __syncthreads();

    int r = tid >> 4;
    int cg = (tid & 15) << 2;
    float a0 = 0.f, a1 = 0.f, a2 = 0.f, a3 = 0.f;
#pragma unroll
    for (int k = 0; k < K; k++) {
        float xv = sx[r][k];
        float4 wv = *(const float4*)&sW[k][cg];
        a0 = fmaf(xv, wv.x, a0);
        a1 = fmaf(xv, wv.y, a1);
        a2 = fmaf(xv, wv.z, a2);
        a3 = fmaf(xv, wv.w, a3);
    }
    int gr = row0 + r;
    if (gr < NN) {
        float4 v = make_float4(a0, a1, a2, a3);
        *(float4*)(g_bufA + (long)gr * DH + cg) = v;
    }
}

// ---------------- gather (+ fused BN stats) ----------------------------------
// bufB[n] = dinv[n]^2*bufA[n] + sum_in bufA[s]*norm; block also reduces its
// 8 rows into per-channel sum/sumsq and atomically adds to g_stats[off..].
// Grid is exactly NN warps (6250 blocks x 8 warps) — no early exits, so the
// epilogue __syncthreads is uniform.
__global__ void k_gather(int off) {
    __shared__ float sSum[64];
    __shared__ float sSq[64];
    if (threadIdx.x < 64) { sSum[threadIdx.x] = 0.f; sSq[threadIdx.x] = 0.f; }
    __syncthreads();

    int warp = (blockIdx.x * blockDim.x + threadIdx.x) >> 5;   // == node id
    int lane = threadIdx.x & 31;
    int half = lane >> 4;
    int c4 = (lane & 15) << 2;

    int beg = g_off[warp];
    int end = g_off[warp + 1];
    int len = end - beg;
    int cnt0 = (len + 1) >> 1;
    int hb = beg + (half ? cnt0 : 0);
    int he = half ? end : beg + cnt0;

    float4 acc = make_float4(0.f, 0.f, 0.f, 0.f);
    if (half == 0) {                       // self loop
        float di = g_deg[warp];
        float w = di * di;
        float4 v = *(const float4*)(g_bufA + (long)warp * DH + c4);
        acc.x = v.x * w; acc.y = v.y * w; acc.z = v.z * w; acc.w = v.w * w;
    }

    int e = hb;
    for (; e + 4 <= he; e += 4) {
        int2 r0 = __ldg(&g_rec[e]);
        int2 r1 = __ldg(&g_rec[e + 1]);
        int2 r2 = __ldg(&g_rec[e + 2]);
        int2 r3 = __ldg(&g_rec[e + 3]);
        float4 v0 = *(const float4*)(g_bufA + (long)r0.x * DH + c4);
        float4 v1 = *(const float4*)(g_bufA + (long)r1.x * DH + c4);
        float4 v2 = *(const float4*)(g_bufA + (long)r2.x * DH + c4);
        float4 v3 = *(const float4*)(g_bufA + (long)r3.x * DH + c4);
        float n0 = __int_as_float(r0.y), n1 = __int_as_float(r1.y);
        float n2 = __int_as_float(r2.y), n3 = __int_as_float(r3.y);
        acc.x = fmaf(v0.x, n0, acc.x); acc.y = fmaf(v0.y, n0, acc.y);
        acc.z = fmaf(v0.z, n0, acc.z); acc.w = fmaf(v0.w, n0, acc.w);
        acc.x = fmaf(v1.x, n1, acc.x); acc.y = fmaf(v1.y, n1, acc.y);
        acc.z = fmaf(v1.z, n1, acc.z); acc.w = fmaf(v1.w, n1, acc.w);
        acc.x = fmaf(v2.x, n2, acc.x); acc.y = fmaf(v2.y, n2, acc.y);
        acc.z = fmaf(v2.z, n2, acc.z); acc.w = fmaf(v2.w, n2, acc.w);
        acc.x = fmaf(v3.x, n3, acc.x); acc.y = fmaf(v3.y, n3, acc.y);
        acc.z = fmaf(v3.z, n3, acc.z); acc.w = fmaf(v3.w, n3, acc.w);
    }
    for (; e < he; e++) {
        int2 r = __ldg(&g_rec[e]);
        float nr = __int_as_float(r.y);
        float4 v = *(const float4*)(g_bufA + (long)r.x * DH + c4);
        acc.x = fmaf(v.x, nr, acc.x);
        acc.y = fmaf(v.y, nr, acc.y);
        acc.z = fmaf(v.z, nr, acc.z);
        acc.w = fmaf(v.w, nr, acc.w);
    }

    acc.x += __shfl_xor_sync(0xFFFFFFFFu, acc.x, 16);
    acc.y += __shfl_xor_sync(0xFFFFFFFFu, acc.y, 16);
    acc.z += __shfl_xor_sync(0xFFFFFFFFu, acc.z, 16);
    acc.w += __shfl_xor_sync(0xFFFFFFFFu, acc.w, 16);

    if (half == 0) {
        *(float4*)(g_bufB + (long)warp * DH + c4) = acc;
        atomicAdd(&sSum[c4 + 0], acc.x);
        atomicAdd(&sSum[c4 + 1], acc.y);
        atomicAdd(&sSum[c4 + 2], acc.z);
        atomicAdd(&sSum[c4 + 3], acc.w);
        atomicAdd(&sSq[c4 + 0], acc.x * acc.x);
        atomicAdd(&sSq[c4 + 1], acc.y * acc.y);
        atomicAdd(&sSq[c4 + 2], acc.z * acc.z);
        atomicAdd(&sSq[c4 + 3], acc.w * acc.w);
    }
    __syncthreads();
    if (threadIdx.x < 64)
        atomicAdd(&g_stats[off + threadIdx.x], sSum[threadIdx.x]);
    else if (threadIdx.x < 128)
        atomicAdd(&g_stats[off + threadIdx.x], sSq[threadIdx.x - 64]);
}

// ---------------- final BN2 + ReLU -> out ------------------------------------
__global__ void k_bnrelu_out(const float* __restrict__ gamma,
                             const float* __restrict__ beta,
                             float* __restrict__ out) {
    int idx = blockIdx.x * blockDim.x + threadIdx.x;
    if (idx >= NN * DH) return;
    int c = idx & 63;
    const float invN = 1.0f / (float)NN;
    float mean = g_stats[128 + c] * invN;
    float var  = g_stats[192 + c] * invN - mean * mean;
    float sc = gamma[c] * rsqrtf(var + BN_EPS);
    float sh = beta[c] - mean * sc;
    out[idx] = fmaxf(fmaf(g_bufB[idx], sc, sh), 0.0f);
}

// ---------------- launch ------------------------------------------------------
extern "C" void kernel_launch(void* const* d_in, const int* in_sizes, int n_in,
                              void* d_out, int out_size) {
    const float* x     = (const float*)d_in[0];
    const int*   ei_sc = (const int*)d_in[1];      // int32! (JAX x64 disabled)
    const float* w_sc  = (const float*)d_in[2];
    /* d_in[3] edge_index_fc unused (matches reference) */
    const float* w_fc  = (const float*)d_in[4];
    const float* alpha = (const float*)d_in[5];
    const float* W1    = (const float*)d_in[6];
    /* d_in[7] b1 cancels in BN */
    const float* W2    = (const float*)d_in[8];
    /* d_in[9] b2 cancels in BN */
    const float* g1    = (const float*)d_in[10];
    const float* be1   = (const float*)d_in[11];
    const float* g2    = (const float*)d_in[12];
    const float* be2   = (const float*)d_in[13];
    float* out = (float*)d_out;

    const int T = 256;
    int gridNV = (NN * DH + T - 1) / T;          // 12500
    int gridE  = (EE + T - 1) / T;               // 6250
    int gridN  = (NN + T - 1) / T;               // 196
    int gridGm = (NN + 15) / 16;                 // 3125
    int gridGa = NN / 8;                         // 6250: exactly NN warps

    // CSR build (shared by both layers)
    k_init<<<gridN, T>>>();
    k_mixdeg<<<gridE, T>>>(ei_sc, w_sc, w_fc, alpha);
    k_scan1<<<NBLK, SCAN_B>>>();                  // + fused dinv
    k_scan3<<<NBLK, SCAN_B>>>();                  // + fused block-sum prefix
    k_fill<<<gridE, T>>>(ei_sc);

    // Layer 1
    k_gemm1<<<gridGm, T>>>(x, W1);
    k_gather<<<gridGa, T>>>(0);                   // + fused BN1 stats

    // Layer 2 (BN1+ReLU fused into GEMM2 load)
    k_gemm2<<<gridGm, T>>>(W2, g1, be1);
    k_gather<<<gridGa, T>>>(128);                 // + fused BN2 stats
    k_bnrelu_out<<<gridNV, T>>>(g2, be2, out);
}